// round 13
// baseline (speedup 1.0000x reference)
#include <cuda_runtime.h>
#include <cuda.h>
#include <cuda_fp16.h>
#include <math.h>
#include <stdint.h>

// ---------------- problem constants ----------------
#define NTOK 8192          // B*S
#define DD   1024          // D
#define EE   8             // experts
#define BM   256           // GEMM M tile
#define BN   128           // GEMM N tile
#define BKH  64            // halves per k-chunk (128 bytes = SW128 atom)
#define KTOT 2048          // split-K': [hi(1024) | corr(1024)]
#define NCH  (KTOT / BKH)  // 32 chunks
#define NST  4             // pipeline stages
#define NTHREADS 544       // 16 compute warps + 1 producer warp
#define NCOMPUTE 512
#define TILE_A_BYTES (BM * 128)              // 32768
#define TILE_B_BYTES (BN * 128)              // 16384
#define STG_BYTES    (TILE_A_BYTES + TILE_B_BYTES)  // 49152
#define SMEM_HDR     3072                    // barriers + stok(1KB) + swt(1KB), padded
#define SMEM_BYTES   (SMEM_HDR + 1024 + NST * STG_BYTES)   // 200704 (incl. align slack)
#define XA_ROWS (2 * NTOK + EE * 256)        // 18432 padded gathered rows

#define ALPHA  0.015625f   // 2^-6
#define INVA   64.0f
#define SCALE1 0.984375f   // 1 - ALPHA

// prep kernel partitioning
#define WCONV_BLOCKS 4096            // (16 k-strips) x (32 n-tiles) x 8 experts
#define GATHER_PER_E (NTOK / 4)      // 2048 blocks, 4 slots each
#define PREP_BLOCKS  (WCONV_BLOCKS + GATHER_PER_E * EE)   // 20480

// ---------------- device scratch (allocation-free) ----------------
__device__ __align__(128) __half g_xa_h[(size_t)XA_ROWS * KTOT];  // ~75MB
__device__ __align__(128) __half g_wb_h[(size_t)EE * DD * KTOT];  // ~33MB
__device__ int   g_cnt[EE];
__device__ int   g_padoff[EE];
__device__ int   g_tok[EE * NTOK];
__device__ float g_wt [EE * NTOK];

// ---------------- PTX helpers ----------------
__device__ __forceinline__ uint32_t smem_u32(const void* p) {
    uint32_t a;
    asm("{ .reg .u64 t; cvta.to.shared.u64 t, %1; cvt.u32.u64 %0, t; }" : "=r"(a) : "l"(p));
    return a;
}

#define SWZ(b) ((b) ^ (((b) >> 3) & 0x70))

#define MBAR_INIT(addr, cnt) \
    asm volatile("mbarrier.init.shared.b64 [%0], %1;" :: "r"(addr), "r"((uint32_t)(cnt)) : "memory")
#define MBAR_EXPECT_TX(addr, bytes) \
    asm volatile("mbarrier.arrive.expect_tx.shared.b64 _, [%0], %1;" :: "r"(addr), "r"((uint32_t)(bytes)) : "memory")
#define MBAR_ARRIVE(addr) \
    asm volatile("mbarrier.arrive.shared.b64 _, [%0];" :: "r"(addr) : "memory")

#define MBAR_WAIT(addr, parity) do {                                              \
    uint32_t _m = (addr); uint32_t _p = (parity); uint32_t _d;                    \
    asm volatile("{\n\t.reg .pred p;\n\t"                                         \
        "mbarrier.try_wait.parity.acquire.cta.shared::cta.b64 p, [%1], %2;\n\t"   \
        "selp.b32 %0, 1, 0, p;\n\t}"                                              \
        : "=r"(_d) : "r"(_m), "r"(_p) : "memory");                                \
    if (!_d) {                                                                    \
        asm volatile("{\n\t.reg .pred P1;\n\t"                                    \
        "WL_%=:\n\t"                                                              \
        "mbarrier.try_wait.parity.acquire.cta.shared::cta.b64 P1, [%0], %1, 0x989680;\n\t" \
        "@P1 bra.uni WD_%=;\n\t"                                                  \
        "bra.uni WL_%=;\n\t"                                                      \
        "WD_%=:\n\t}" :: "r"(_m), "r"(_p) : "memory");                            \
    }                                                                             \
} while (0)

#define TMA2D(dst, map, cx, cy, mbar) \
    asm volatile("cp.async.bulk.tensor.2d.shared::cta.global.tile.mbarrier::complete_tx::bytes " \
                 "[%0], [%1, {%2, %3}], [%4];" \
                 :: "r"(dst), "l"(map), "r"((int)(cx)), "r"((int)(cy)), "r"(mbar) : "memory")

#define LDSM_X4(r, addr) \
    asm volatile("ldmatrix.sync.aligned.m8n8.x4.shared.b16 {%0,%1,%2,%3}, [%4];" \
        : "=r"((r)[0]), "=r"((r)[1]), "=r"((r)[2]), "=r"((r)[3]) : "r"(addr))

__device__ __forceinline__ void mma16816(float* d, const uint32_t* a,
                                         uint32_t b0, uint32_t b1) {
    asm volatile("mma.sync.aligned.m16n8k16.row.col.f32.f16.f16.f32 "
        "{%0,%1,%2,%3}, {%4,%5,%6,%7}, {%8,%9}, {%0,%1,%2,%3};"
        : "+f"(d[0]), "+f"(d[1]), "+f"(d[2]), "+f"(d[3])
        : "r"(a[0]), "r"(a[1]), "r"(a[2]), "r"(a[3]), "r"(b0), "r"(b1));
}

// ---------------- kernel 1: reset counters ----------------
__global__ void reset_kernel() {
    if (threadIdx.x < EE) g_cnt[threadIdx.x] = 0;
}

// ---------------- kernel 2: gating / routing (one warp per token) ----------------
__global__ void gate_kernel(const float* __restrict__ x,
                            const float* __restrict__ Wg,
                            const float* __restrict__ bg) {
    int gwarp = (blockIdx.x * blockDim.x + threadIdx.x) >> 5;
    int lane  = threadIdx.x & 31;
    if (gwarp >= NTOK) return;

    const float* xr = x + (size_t)gwarp * DD;
    float acc[EE];
#pragma unroll
    for (int e = 0; e < EE; e++) acc[e] = 0.f;

    for (int d = lane; d < DD; d += 32) {
        float xv = xr[d];
        const float4* wr = reinterpret_cast<const float4*>(Wg + (size_t)d * EE);
        float4 w0 = wr[0];
        float4 w1 = wr[1];
        acc[0] += xv * w0.x; acc[1] += xv * w0.y;
        acc[2] += xv * w0.z; acc[3] += xv * w0.w;
        acc[4] += xv * w1.x; acc[5] += xv * w1.y;
        acc[6] += xv * w1.z; acc[7] += xv * w1.w;
    }
#pragma unroll
    for (int e = 0; e < EE; e++) {
#pragma unroll
        for (int off = 16; off > 0; off >>= 1)
            acc[e] += __shfl_xor_sync(0xffffffffu, acc[e], off);
    }

    if (lane == 0) {
        float s[EE];
#pragma unroll
        for (int e = 0; e < EE; e++) s[e] = acc[e] + bg[e];
        int i0 = 0;
#pragma unroll
        for (int e = 1; e < EE; e++) if (s[e] > s[i0]) i0 = e;
        int i1 = (i0 == 0) ? 1 : 0;
#pragma unroll
        for (int e = 0; e < EE; e++) if (e != i0 && s[e] > s[i1]) i1 = e;

        float w0 = 1.f / (1.f + expf(s[i1] - s[i0]));
        float w1 = 1.f - w0;

        int p0 = atomicAdd(&g_cnt[i0], 1);
        g_tok[i0 * NTOK + p0] = gwarp;
        g_wt [i0 * NTOK + p0] = w0;
        int p1 = atomicAdd(&g_cnt[i1], 1);
        g_tok[i1 * NTOK + p1] = gwarp;
        g_wt [i1 * NTOK + p1] = w1;
    }
}

// ---------------- kernel 3: padded prefix offsets ----------------
__global__ void offsets_kernel() {
    if (threadIdx.x == 0) {
        int off = 0;
        for (int e = 0; e < EE; e++) {
            g_padoff[e] = off;
            off += ((g_cnt[e] + BM - 1) / BM) * BM;
        }
    }
}

// ---------------- kernel 4: FUSED prep: wconv + gather ----------------
__global__ void __launch_bounds__(256)
prep_kernel(const float* __restrict__ x, const float* __restrict__ We) {
    int bid = blockIdx.x;
    int tid = threadIdx.x;

    if (bid < WCONV_BLOCKS) {
        __shared__ float t[64][33];
        int e  = bid >> 9;                 // 512 tiles per expert
        int r  = bid & 511;
        int k0 = (r & 15) * 64;            // 16 k-strips
        int n0 = (r >> 4) * 32;            // 32 n-tiles
        const float* src = We + ((size_t)e << 20);
        __half* dst = g_wb_h + (size_t)e * DD * KTOT;

#pragma unroll
        for (int i = 0; i < 8; i++) {
            int kk = (tid >> 5) + i * 8;   // 0..63
            int nn = tid & 31;
            t[kk][nn] = src[(size_t)(k0 + kk) * DD + n0 + nn];
        }
        __syncthreads();

        int nn  = tid >> 3;                // 0..31
        int kk0 = (tid & 7) * 8;           // 0..56
        size_t rowo = (size_t)(n0 + nn) * KTOT + k0 + kk0;
        __half hb[8], cb[8];
#pragma unroll
        for (int i = 0; i < 8; i++) {
            float w = t[kk0 + i][nn];
            __half wh = __float2half_rn(w);
            float whf = __half2float(wh);
            hb[i] = wh;
            cb[i] = __float2half_rn(whf + INVA * (w - whf));
        }
        *reinterpret_cast<uint4*>(dst + rowo)      = *reinterpret_cast<uint4*>(hb);
        *reinterpret_cast<uint4*>(dst + rowo + DD) = *reinterpret_cast<uint4*>(cb);
    } else {
        int b    = bid - WCONV_BLOCKS;
        int e    = b / GATHER_PER_E;
        int base = (b % GATHER_PER_E) * 4;
        int cnt  = g_cnt[e];
        if (base >= cnt) return;
        int slot = base + (tid >> 6);
        if (slot >= cnt) return;
        int tok = g_tok[e * NTOK + slot];
        size_t row = (size_t)(g_padoff[e] + slot);
        const float4* src = reinterpret_cast<const float4*>(x + (size_t)tok * DD);
        __half2* d0 = reinterpret_cast<__half2*>(g_xa_h + row * KTOT);
        __half2* d1 = reinterpret_cast<__half2*>(g_xa_h + row * KTOT + DD);
        int i0 = tid & 63;
#pragma unroll
        for (int j = 0; j < 4; j++) {
            int i = i0 + j * 64;           // 0..255
            float4 v = src[i];
            __half h0 = __float2half_rn(v.x), h1 = __float2half_rn(v.y);
            __half h2 = __float2half_rn(v.z), h3 = __float2half_rn(v.w);
            float f0 = __half2float(h0), f1 = __half2float(h1);
            float f2 = __half2float(h2), f3 = __half2float(h3);
            __half c0 = __float2half_rn((v.x - f0) + ALPHA * f0);
            __half c1 = __float2half_rn((v.y - f1) + ALPHA * f1);
            __half c2 = __float2half_rn((v.z - f2) + ALPHA * f2);
            __half c3 = __float2half_rn((v.w - f3) + ALPHA * f3);
            d0[i * 2]     = __halves2half2(h0, h1);
            d0[i * 2 + 1] = __halves2half2(h2, h3);
            d1[i * 2]     = __halves2half2(c0, c1);
            d1[i * 2 + 1] = __halves2half2(c2, c3);
        }
    }
}

// ---------------- kernel 5: TMA + mma.sync fp16 grouped GEMM --------------------
// 256x128 tile. 16 compute warps (4m x 2n... -> 4m x 4n, each 64x32) + 1 producer warp.
// D = (1-a)*sum(xh*wh) + sum((xl+a*xh)*(wh+wl/a)) = x*w + O(2^-18)
__global__ void __launch_bounds__(NTHREADS, 1)
moe_gemm_hmma(const __grid_constant__ CUtensorMap tma_a,
              const __grid_constant__ CUtensorMap tma_b,
              const float* __restrict__ be,
              float* __restrict__ out) {
    int e   = blockIdx.z;
    int cnt = g_cnt[e];
    int m0  = blockIdx.y * BM;
    if (m0 >= cnt) return;
    int rows = min(BM, cnt - m0);
    int n0   = blockIdx.x * BN;
    int arow = g_padoff[e] + m0;
    int brow = e * DD + n0;

    extern __shared__ char smem[];
    uint32_t sb = smem_u32(smem);
    uint32_t FULLB  = sb;                      // 4 x 8B
    uint32_t EMPTYB = sb + 32;                 // 4 x 8B
    int*   stok = reinterpret_cast<int*>(smem + 64);           // 256 ints
    float* swt  = reinterpret_cast<float*>(smem + 64 + 1024);  // 256 floats
    uint32_t tb = (sb + SMEM_HDR + 1023) & ~1023u;             // tile base

    int tid = threadIdx.x, lane = tid & 31, wid = tid >> 5;

    if (tid < BM) {
        int idx = e * NTOK + m0 + tid;
        stok[tid] = (tid < rows) ? g_tok[idx] : 0;
        swt [tid] = (tid < rows) ? g_wt[idx] : 0.f;
    }
    if (tid == 0) {
        for (int s = 0; s < NST; s++) {
            MBAR_INIT(FULLB + s * 8, 1);
            MBAR_INIT(EMPTYB + s * 8, NCOMPUTE);
        }
    }
    __syncthreads();

    if (wid == 16) {
        // ---- dedicated producer warp ----
        if (lane == 0) {
            for (int s = 0; s < NST; s++) {
                MBAR_EXPECT_TX(FULLB + s * 8, STG_BYTES);
                TMA2D(tb + s * STG_BYTES,                &tma_a, s * BKH, arow, FULLB + s * 8);
                TMA2D(tb + s * STG_BYTES + TILE_A_BYTES, &tma_b, s * BKH, brow, FULLB + s * 8);
            }
            for (int c = NST; c < NCH; c++) {
                int s  = c & (NST - 1);
                int ph = ((c - NST) >> 2) & 1;   // parity of slot's last consumption
                MBAR_WAIT(EMPTYB + s * 8, ph);
                MBAR_EXPECT_TX(FULLB + s * 8, STG_BYTES);
                TMA2D(tb + s * STG_BYTES,                &tma_a, c * BKH, arow, FULLB + s * 8);
                TMA2D(tb + s * STG_BYTES + TILE_A_BYTES, &tma_b, c * BKH, brow, FULLB + s * 8);
            }
        }
        return;  // producer warp does no epilogue
    }

    // ---- compute warps: 4m x 4n, each 64(m) x 32(n) ----
    int warp_m = wid & 3, warp_n = wid >> 2;

    uint32_t a_off = (uint32_t)(warp_m * 64 + (lane & 15)) * 128 + ((lane >> 4) << 4);
    uint32_t b_off = (uint32_t)(warp_n * 32 + (lane & 7) + ((lane >> 4) << 3)) * 128
                     + (((lane >> 3) & 1) << 4);

    float acc[4][4][4];
#pragma unroll
    for (int i = 0; i < 4; i++)
#pragma unroll
        for (int j = 0; j < 4; j++)
#pragma unroll
            for (int k = 0; k < 4; k++) acc[i][j][k] = 0.f;

    for (int c = 0; c < NCH; c++) {
        int s  = c & (NST - 1);
        int ph = (c >> 2) & 1;
        MBAR_WAIT(FULLB + s * 8, ph);
        if (c == NCH / 2) {   // chain boundary: D *= (1 - alpha)
#pragma unroll
            for (int i = 0; i < 4; i++)
#pragma unroll
                for (int j = 0; j < 4; j++)
#pragma unroll
                    for (int k = 0; k < 4; k++) acc[i][j][k] *= SCALE1;
        }
        uint32_t As = tb + s * STG_BYTES;
        uint32_t Bs = As + TILE_A_BYTES;
#pragma unroll
        for (int ks = 0; ks < 4; ks++) {
            uint32_t a[4][4], b[2][4];
            uint32_t kb = (uint32_t)ks * 32;
#pragma unroll
            for (int mt = 0; mt < 4; mt++) {
                uint32_t o = a_off + (uint32_t)mt * 2048 + kb;
                LDSM_X4(a[mt], As + SWZ(o));
            }
#pragma unroll
            for (int np = 0; np < 2; np++) {
                uint32_t o = b_off + (uint32_t)np * 2048 + kb;
                LDSM_X4(b[np], Bs + SWZ(o));
            }
#pragma unroll
            for (int mt = 0; mt < 4; mt++)
#pragma unroll
                for (int nt = 0; nt < 4; nt++)
                    mma16816(acc[mt][nt], a[mt],
                             b[nt >> 1][(nt & 1) * 2], b[nt >> 1][(nt & 1) * 2 + 1]);
        }
        MBAR_ARRIVE(EMPTYB + s * 8);
    }

    // ---- epilogue: out[tok, n] += w * (acc + be[e, n]) (2 contribs/elem) ----
    const float* beg = be + (size_t)e * DD + n0;
#pragma unroll
    for (int mt = 0; mt < 4; mt++) {
#pragma unroll
        for (int rh = 0; rh < 2; rh++) {
            int ml = warp_m * 64 + mt * 16 + (lane >> 2) + rh * 8;
            if (ml < rows) {
                int   tok = stok[ml];
                float w   = swt[ml];
                float* orow = out + (size_t)tok * DD + n0;
#pragma unroll
                for (int nt = 0; nt < 4; nt++) {
                    int nl = warp_n * 32 + nt * 8 + (lane & 3) * 2;
                    atomicAdd(orow + nl,     w * (acc[mt][nt][rh * 2]     + beg[nl]));
                    atomicAdd(orow + nl + 1, w * (acc[mt][nt][rh * 2 + 1] + beg[nl + 1]));
                }
            }
        }
    }
}

// ---------------- host launch ----------------
typedef CUresult (*EncodeFn)(CUtensorMap*, CUtensorMapDataType, cuuint32_t, void*,
                             const cuuint64_t*, const cuuint64_t*, const cuuint32_t*,
                             const cuuint32_t*, CUtensorMapInterleave, CUtensorMapSwizzle,
                             CUtensorMapL2promotion, CUtensorMapFloatOOBfill);

extern "C" void kernel_launch(void* const* d_in, const int* in_sizes, int n_in,
                              void* d_out, int out_size) {
    const float* x  = (const float*)d_in[0];   // [B,S,D]
    const float* Wg = (const float*)d_in[1];   // [D,E]
    const float* bg = (const float*)d_in[2];   // [E]
    const float* We = (const float*)d_in[3];   // [E,D,D]
    const float* be = (const float*)d_in[4];   // [E,D]
    float* out = (float*)d_out;                // [B,S,D]

    EncodeFn encode = nullptr;
    cudaDriverEntryPointQueryResult qr;
    cudaGetDriverEntryPoint("cuTensorMapEncodeTiled", (void**)&encode,
                            cudaEnableDefault, &qr);

    void* xa_ptr = nullptr; cudaGetSymbolAddress(&xa_ptr, g_xa_h);
    void* wb_ptr = nullptr; cudaGetSymbolAddress(&wb_ptr, g_wb_h);

    CUtensorMap tma_a{}, tma_b{};
    {
        cuuint64_t dims[2]    = {KTOT, XA_ROWS};
        cuuint64_t strides[1] = {KTOT * sizeof(__half)};
        cuuint32_t box[2]     = {BKH, BM};
        cuuint32_t es[2]      = {1, 1};
        encode(&tma_a, CU_TENSOR_MAP_DATA_TYPE_FLOAT16, 2, xa_ptr, dims, strides, box, es,
               CU_TENSOR_MAP_INTERLEAVE_NONE, CU_TENSOR_MAP_SWIZZLE_128B,
               CU_TENSOR_MAP_L2_PROMOTION_L2_128B, CU_TENSOR_MAP_FLOAT_OOB_FILL_NONE);
    }
    {
        cuuint64_t dims[2]    = {KTOT, (cuuint64_t)EE * DD};
        cuuint64_t strides[1] = {KTOT * sizeof(__half)};
        cuuint32_t box[2]     = {BKH, BN};
        cuuint32_t es[2]      = {1, 1};
        encode(&tma_b, CU_TENSOR_MAP_DATA_TYPE_FLOAT16, 2, wb_ptr, dims, strides, box, es,
               CU_TENSOR_MAP_INTERLEAVE_NONE, CU_TENSOR_MAP_SWIZZLE_128B,
               CU_TENSOR_MAP_L2_PROMOTION_L2_128B, CU_TENSOR_MAP_FLOAT_OOB_FILL_NONE);
    }

    cudaFuncSetAttribute(moe_gemm_hmma, cudaFuncAttributeMaxDynamicSharedMemorySize, SMEM_BYTES);

    cudaMemsetAsync(d_out, 0, (size_t)out_size * sizeof(float));
    reset_kernel<<<1, 32>>>();
    gate_kernel<<<NTOK / 8, 256>>>(x, Wg, bg);
    offsets_kernel<<<1, 32>>>();
    prep_kernel<<<PREP_BLOCKS, 256>>>(x, We);

    dim3 grid(DD / BN, NTOK / BM, EE);   // (8, 32, 8); empty M-tiles early-exit
    moe_gemm_hmma<<<grid, NTHREADS, SMEM_BYTES>>>(tma_a, tma_b, be, out);
}

// round 15
// speedup vs baseline: 1.6005x; 1.6005x over previous
#include <cuda_runtime.h>
#include <cuda.h>
#include <cuda_fp16.h>
#include <math.h>
#include <stdint.h>

// ---------------- problem constants ----------------
#define NTOK 8192          // B*S
#define DD   1024          // D
#define EE   8             // experts
#define BM   256           // GEMM M tile
#define BN   128           // GEMM N tile
#define BKH  64            // halves per k-chunk (128 bytes = SW128 atom)
#define KTOT 1024          // single fp16 chain (K = D)
#define NCH  (KTOT / BKH)  // 16 chunks
#define NST  4             // pipeline stages
#define TILE_A_BYTES (BM * 128)              // 32768
#define TILE_B_BYTES (BN * 128)              // 16384
#define STG_BYTES    (TILE_A_BYTES + TILE_B_BYTES)  // 49152
#define SMEM_HDR     3072                    // barriers + stok(1KB) + swt(1KB), padded
#define SMEM_BYTES   (SMEM_HDR + 1024 + NST * STG_BYTES)   // 200704 (incl. align slack)
#define XA_ROWS (2 * NTOK + EE * 256)        // 18432 padded gathered rows

// prep kernel partitioning
#define WCONV_BLOCKS 4096            // (16 k-strips) x (32 n-tiles) x 8 experts
#define GATHER_PER_E (NTOK / 4)      // 2048 blocks, 4 slots each
#define PREP_BLOCKS  (WCONV_BLOCKS + GATHER_PER_E * EE)   // 20480

// ---------------- device scratch (allocation-free) ----------------
__device__ __align__(128) __half g_xa_h[(size_t)XA_ROWS * KTOT];  // ~37MB
__device__ __align__(128) __half g_wb_h[(size_t)EE * DD * KTOT];  // ~16MB
__device__ int   g_cnt[EE];
__device__ int   g_padoff[EE];
__device__ int   g_tok[EE * NTOK];
__device__ float g_wt [EE * NTOK];

// ---------------- PTX helpers ----------------
__device__ __forceinline__ uint32_t smem_u32(const void* p) {
    uint32_t a;
    asm("{ .reg .u64 t; cvta.to.shared.u64 t, %1; cvt.u32.u64 %0, t; }" : "=r"(a) : "l"(p));
    return a;
}

#define SWZ(b) ((b) ^ (((b) >> 3) & 0x70))

#define MBAR_INIT(addr, cnt) \
    asm volatile("mbarrier.init.shared.b64 [%0], %1;" :: "r"(addr), "r"((uint32_t)(cnt)) : "memory")
#define MBAR_EXPECT_TX(addr, bytes) \
    asm volatile("mbarrier.arrive.expect_tx.shared.b64 _, [%0], %1;" :: "r"(addr), "r"((uint32_t)(bytes)) : "memory")
#define MBAR_ARRIVE(addr) \
    asm volatile("mbarrier.arrive.shared.b64 _, [%0];" :: "r"(addr) : "memory")

#define MBAR_WAIT(addr, parity) do {                                              \
    uint32_t _m = (addr); uint32_t _p = (parity); uint32_t _d;                    \
    asm volatile("{\n\t.reg .pred p;\n\t"                                         \
        "mbarrier.try_wait.parity.acquire.cta.shared::cta.b64 p, [%1], %2;\n\t"   \
        "selp.b32 %0, 1, 0, p;\n\t}"                                              \
        : "=r"(_d) : "r"(_m), "r"(_p) : "memory");                                \
    if (!_d) {                                                                    \
        asm volatile("{\n\t.reg .pred P1;\n\t"                                    \
        "WL_%=:\n\t"                                                              \
        "mbarrier.try_wait.parity.acquire.cta.shared::cta.b64 P1, [%0], %1, 0x989680;\n\t" \
        "@P1 bra.uni WD_%=;\n\t"                                                  \
        "bra.uni WL_%=;\n\t"                                                      \
        "WD_%=:\n\t}" :: "r"(_m), "r"(_p) : "memory");                            \
    }                                                                             \
} while (0)

#define TMA2D(dst, map, cx, cy, mbar) \
    asm volatile("cp.async.bulk.tensor.2d.shared::cta.global.tile.mbarrier::complete_tx::bytes " \
                 "[%0], [%1, {%2, %3}], [%4];" \
                 :: "r"(dst), "l"(map), "r"((int)(cx)), "r"((int)(cy)), "r"(mbar) : "memory")

#define LDSM_X4(r, addr) \
    asm volatile("ldmatrix.sync.aligned.m8n8.x4.shared.b16 {%0,%1,%2,%3}, [%4];" \
        : "=r"((r)[0]), "=r"((r)[1]), "=r"((r)[2]), "=r"((r)[3]) : "r"(addr))

__device__ __forceinline__ void mma16816(float* d, const uint32_t* a,
                                         uint32_t b0, uint32_t b1) {
    asm volatile("mma.sync.aligned.m16n8k16.row.col.f32.f16.f16.f32 "
        "{%0,%1,%2,%3}, {%4,%5,%6,%7}, {%8,%9}, {%0,%1,%2,%3};"
        : "+f"(d[0]), "+f"(d[1]), "+f"(d[2]), "+f"(d[3])
        : "r"(a[0]), "r"(a[1]), "r"(a[2]), "r"(a[3]), "r"(b0), "r"(b1));
}

// ---------------- kernel 1: reset counters ----------------
__global__ void reset_kernel() {
    if (threadIdx.x < EE) g_cnt[threadIdx.x] = 0;
}

// ---------------- kernel 2: gating / routing (one warp per token) ----------------
__global__ void gate_kernel(const float* __restrict__ x,
                            const float* __restrict__ Wg,
                            const float* __restrict__ bg) {
    int gwarp = (blockIdx.x * blockDim.x + threadIdx.x) >> 5;
    int lane  = threadIdx.x & 31;
    if (gwarp >= NTOK) return;

    const float* xr = x + (size_t)gwarp * DD;
    float acc[EE];
#pragma unroll
    for (int e = 0; e < EE; e++) acc[e] = 0.f;

    for (int d = lane; d < DD; d += 32) {
        float xv = xr[d];
        const float4* wr = reinterpret_cast<const float4*>(Wg + (size_t)d * EE);
        float4 w0 = wr[0];
        float4 w1 = wr[1];
        acc[0] += xv * w0.x; acc[1] += xv * w0.y;
        acc[2] += xv * w0.z; acc[3] += xv * w0.w;
        acc[4] += xv * w1.x; acc[5] += xv * w1.y;
        acc[6] += xv * w1.z; acc[7] += xv * w1.w;
    }
#pragma unroll
    for (int e = 0; e < EE; e++) {
#pragma unroll
        for (int off = 16; off > 0; off >>= 1)
            acc[e] += __shfl_xor_sync(0xffffffffu, acc[e], off);
    }

    if (lane == 0) {
        float s[EE];
#pragma unroll
        for (int e = 0; e < EE; e++) s[e] = acc[e] + bg[e];
        int i0 = 0;
#pragma unroll
        for (int e = 1; e < EE; e++) if (s[e] > s[i0]) i0 = e;
        int i1 = (i0 == 0) ? 1 : 0;
#pragma unroll
        for (int e = 0; e < EE; e++) if (e != i0 && s[e] > s[i1]) i1 = e;

        float w0 = 1.f / (1.f + expf(s[i1] - s[i0]));
        float w1 = 1.f - w0;

        int p0 = atomicAdd(&g_cnt[i0], 1);
        g_tok[i0 * NTOK + p0] = gwarp;
        g_wt [i0 * NTOK + p0] = w0;
        int p1 = atomicAdd(&g_cnt[i1], 1);
        g_tok[i1 * NTOK + p1] = gwarp;
        g_wt [i1 * NTOK + p1] = w1;
    }
}

// ---------------- kernel 3: padded prefix offsets ----------------
__global__ void offsets_kernel() {
    if (threadIdx.x == 0) {
        int off = 0;
        for (int e = 0; e < EE; e++) {
            g_padoff[e] = off;
            off += ((g_cnt[e] + BM - 1) / BM) * BM;
        }
    }
}

// ---------------- kernel 4: FUSED prep: wconv + gather (fp16, single chain) ------
__global__ void __launch_bounds__(256)
prep_kernel(const float* __restrict__ x, const float* __restrict__ We) {
    int bid = blockIdx.x;
    int tid = threadIdx.x;

    if (bid < WCONV_BLOCKS) {
        __shared__ float t[64][33];
        int e  = bid >> 9;                 // 512 tiles per expert
        int r  = bid & 511;
        int k0 = (r & 15) * 64;            // 16 k-strips
        int n0 = (r >> 4) * 32;            // 32 n-tiles
        const float* src = We + ((size_t)e << 20);
        __half* dst = g_wb_h + (size_t)e * DD * KTOT;

#pragma unroll
        for (int i = 0; i < 8; i++) {
            int kk = (tid >> 5) + i * 8;   // 0..63
            int nn = tid & 31;
            t[kk][nn] = src[(size_t)(k0 + kk) * DD + n0 + nn];
        }
        __syncthreads();

        int nn  = tid >> 3;                // 0..31
        int kk0 = (tid & 7) * 8;           // 0..56
        size_t rowo = (size_t)(n0 + nn) * KTOT + k0 + kk0;
        __half hb[8];
#pragma unroll
        for (int i = 0; i < 8; i++)
            hb[i] = __float2half_rn(t[kk0 + i][nn]);
        *reinterpret_cast<uint4*>(dst + rowo) = *reinterpret_cast<uint4*>(hb);
    } else {
        int b    = bid - WCONV_BLOCKS;
        int e    = b / GATHER_PER_E;
        int base = (b % GATHER_PER_E) * 4;
        int cnt  = g_cnt[e];
        if (base >= cnt) return;
        int slot = base + (tid >> 6);
        if (slot >= cnt) return;
        int tok = g_tok[e * NTOK + slot];
        size_t row = (size_t)(g_padoff[e] + slot);
        const float4* src = reinterpret_cast<const float4*>(x + (size_t)tok * DD);
        __half2* d0 = reinterpret_cast<__half2*>(g_xa_h + row * KTOT);
        int i0 = tid & 63;
#pragma unroll
        for (int j = 0; j < 4; j++) {
            int i = i0 + j * 64;           // 0..255
            float4 v = src[i];
            d0[i * 2]     = __halves2half2(__float2half_rn(v.x), __float2half_rn(v.y));
            d0[i * 2 + 1] = __halves2half2(__float2half_rn(v.z), __float2half_rn(v.w));
        }
    }
}

// ---------------- kernel 5: TMA + mma.sync fp16 grouped GEMM --------------------
// 256x128 tile, 256 threads (8 warps = 4m x 2n, each 64x64). Single fp16 chain.
__global__ void __launch_bounds__(256, 1)
moe_gemm_hmma(const __grid_constant__ CUtensorMap tma_a,
              const __grid_constant__ CUtensorMap tma_b,
              const float* __restrict__ be,
              float* __restrict__ out) {
    int e   = blockIdx.z;
    int cnt = g_cnt[e];
    int m0  = blockIdx.y * BM;
    if (m0 >= cnt) return;
    int rows = min(BM, cnt - m0);
    int n0   = blockIdx.x * BN;
    int arow = g_padoff[e] + m0;
    int brow = e * DD + n0;

    extern __shared__ char smem[];
    uint32_t sb = smem_u32(smem);
    uint32_t FULLB  = sb;                      // 4 x 8B
    uint32_t EMPTYB = sb + 32;                 // 4 x 8B
    int*   stok = reinterpret_cast<int*>(smem + 64);           // 256 ints
    float* swt  = reinterpret_cast<float*>(smem + 64 + 1024);  // 256 floats
    uint32_t tb = (sb + SMEM_HDR + 1023) & ~1023u;             // tile base

    int tid = threadIdx.x, lane = tid & 31, wid = tid >> 5;
    int warp_m = wid & 3, warp_n = wid >> 2;

    {
        int idx = e * NTOK + m0 + tid;
        stok[tid] = (tid < rows) ? g_tok[idx] : 0;
        swt [tid] = (tid < rows) ? g_wt[idx] : 0.f;
    }
    if (tid == 0) {
        for (int s = 0; s < NST; s++) {
            MBAR_INIT(FULLB + s * 8, 1);
            MBAR_INIT(EMPTYB + s * 8, 256);
        }
    }
    __syncthreads();

    if (tid == 0) {
        for (int s = 0; s < NST; s++) {
            MBAR_EXPECT_TX(FULLB + s * 8, STG_BYTES);
            TMA2D(tb + s * STG_BYTES,                &tma_a, s * BKH, arow, FULLB + s * 8);
            TMA2D(tb + s * STG_BYTES + TILE_A_BYTES, &tma_b, s * BKH, brow, FULLB + s * 8);
        }
    }

    // ldmatrix byte offsets within 128B-row tiles
    uint32_t a_off = (uint32_t)(warp_m * 64 + (lane & 15)) * 128 + ((lane >> 4) << 4);
    uint32_t b_off = (uint32_t)(warp_n * 64 + (lane & 7) + ((lane >> 4) << 3)) * 128
                     + (((lane >> 3) & 1) << 4);

    float acc[4][8][4];
#pragma unroll
    for (int i = 0; i < 4; i++)
#pragma unroll
        for (int j = 0; j < 8; j++)
#pragma unroll
            for (int k = 0; k < 4; k++) acc[i][j][k] = 0.f;

    for (int c = 0; c < NCH; c++) {
        int s  = c & (NST - 1);
        int ph = (c >> 2) & 1;
        MBAR_WAIT(FULLB + s * 8, ph);
        uint32_t As = tb + s * STG_BYTES;
        uint32_t Bs = As + TILE_A_BYTES;
#pragma unroll
        for (int ks = 0; ks < 4; ks++) {
            uint32_t a[4][4], b[4][4];
            uint32_t kb = (uint32_t)ks * 32;
#pragma unroll
            for (int mt = 0; mt < 4; mt++) {
                uint32_t o = a_off + (uint32_t)mt * 2048 + kb;
                LDSM_X4(a[mt], As + SWZ(o));
            }
#pragma unroll
            for (int np = 0; np < 4; np++) {
                uint32_t o = b_off + (uint32_t)np * 2048 + kb;
                LDSM_X4(b[np], Bs + SWZ(o));
            }
#pragma unroll
            for (int mt = 0; mt < 4; mt++)
#pragma unroll
                for (int nt = 0; nt < 8; nt++)
                    mma16816(acc[mt][nt], a[mt],
                             b[nt >> 1][(nt & 1) * 2], b[nt >> 1][(nt & 1) * 2 + 1]);
        }
        MBAR_ARRIVE(EMPTYB + s * 8);
        if (tid == 0 && c + NST < NCH) {
            MBAR_WAIT(EMPTYB + s * 8, ph);
            MBAR_EXPECT_TX(FULLB + s * 8, STG_BYTES);
            TMA2D(As, &tma_a, (c + NST) * BKH, arow, FULLB + s * 8);
            TMA2D(Bs, &tma_b, (c + NST) * BKH, brow, FULLB + s * 8);
        }
    }

    // ---- epilogue: out[tok, n] += w * (acc + be[e, n]) (2 contribs/elem) ----
    const float* beg = be + (size_t)e * DD + n0;
#pragma unroll
    for (int mt = 0; mt < 4; mt++) {
#pragma unroll
        for (int rh = 0; rh < 2; rh++) {
            int ml = warp_m * 64 + mt * 16 + (lane >> 2) + rh * 8;
            if (ml < rows) {
                int   tok = stok[ml];
                float w   = swt[ml];
                float* orow = out + (size_t)tok * DD + n0;
#pragma unroll
                for (int nt = 0; nt < 8; nt++) {
                    int nl = warp_n * 64 + nt * 8 + (lane & 3) * 2;
                    atomicAdd(orow + nl,     w * (acc[mt][nt][rh * 2]     + beg[nl]));
                    atomicAdd(orow + nl + 1, w * (acc[mt][nt][rh * 2 + 1] + beg[nl + 1]));
                }
            }
        }
    }
}

// ---------------- host launch ----------------
typedef CUresult (*EncodeFn)(CUtensorMap*, CUtensorMapDataType, cuuint32_t, void*,
                             const cuuint64_t*, const cuuint64_t*, const cuuint32_t*,
                             const cuuint32_t*, CUtensorMapInterleave, CUtensorMapSwizzle,
                             CUtensorMapL2promotion, CUtensorMapFloatOOBfill);

extern "C" void kernel_launch(void* const* d_in, const int* in_sizes, int n_in,
                              void* d_out, int out_size) {
    const float* x  = (const float*)d_in[0];   // [B,S,D]
    const float* Wg = (const float*)d_in[1];   // [D,E]
    const float* bg = (const float*)d_in[2];   // [E]
    const float* We = (const float*)d_in[3];   // [E,D,D]
    const float* be = (const float*)d_in[4];   // [E,D]
    float* out = (float*)d_out;                // [B,S,D]

    EncodeFn encode = nullptr;
    cudaDriverEntryPointQueryResult qr;
    cudaGetDriverEntryPoint("cuTensorMapEncodeTiled", (void**)&encode,
                            cudaEnableDefault, &qr);

    void* xa_ptr = nullptr; cudaGetSymbolAddress(&xa_ptr, g_xa_h);
    void* wb_ptr = nullptr; cudaGetSymbolAddress(&wb_ptr, g_wb_h);

    CUtensorMap tma_a{}, tma_b{};
    {
        cuuint64_t dims[2]    = {KTOT, XA_ROWS};
        cuuint64_t strides[1] = {KTOT * sizeof(__half)};
        cuuint32_t box[2]     = {BKH, BM};
        cuuint32_t es[2]      = {1, 1};
        encode(&tma_a, CU_TENSOR_MAP_DATA_TYPE_FLOAT16, 2, xa_ptr, dims, strides, box, es,
               CU_TENSOR_MAP_INTERLEAVE_NONE, CU_TENSOR_MAP_SWIZZLE_128B,
               CU_TENSOR_MAP_L2_PROMOTION_L2_128B, CU_TENSOR_MAP_FLOAT_OOB_FILL_NONE);
    }
    {
        cuuint64_t dims[2]    = {KTOT, (cuuint64_t)EE * DD};
        cuuint64_t strides[1] = {KTOT * sizeof(__half)};
        cuuint32_t box[2]     = {BKH, BN};
        cuuint32_t es[2]      = {1, 1};
        encode(&tma_b, CU_TENSOR_MAP_DATA_TYPE_FLOAT16, 2, wb_ptr, dims, strides, box, es,
               CU_TENSOR_MAP_INTERLEAVE_NONE, CU_TENSOR_MAP_SWIZZLE_128B,
               CU_TENSOR_MAP_L2_PROMOTION_L2_128B, CU_TENSOR_MAP_FLOAT_OOB_FILL_NONE);
    }

    cudaFuncSetAttribute(moe_gemm_hmma, cudaFuncAttributeMaxDynamicSharedMemorySize, SMEM_BYTES);

    cudaMemsetAsync(d_out, 0, (size_t)out_size * sizeof(float));
    reset_kernel<<<1, 32>>>();
    gate_kernel<<<NTOK / 8, 256>>>(x, Wg, bg);
    offsets_kernel<<<1, 32>>>();
    prep_kernel<<<PREP_BLOCKS, 256>>>(x, We);

    dim3 grid(DD / BN, NTOK / BM, EE);   // (8, 32, 8); empty M-tiles early-exit
    moe_gemm_hmma<<<grid, 256, SMEM_BYTES>>>(tma_a, tma_b, be, out);
}